// round 1
// baseline (speedup 1.0000x reference)
#include <cuda_runtime.h>

// Problem constants (fixed by setup_inputs, seed 0)
#define BIGZ 1000000.0f
constexpr int N_ = 8, H_ = 512, W_ = 512, C_ = 32, F_ = 20000, V_ = 10002;
constexpr int HW = H_ * W_;  // 262144

// Output concatenation offsets (in float32 elements)
constexpr long long OFF_OUTMAP = 0LL;          // 8*32*HW = 67108864
constexpr long long OFF_VV     = 67108864LL;   // 10002
constexpr long long OFF_MASK   = 67118866LL;   // 8*HW
constexpr long long OFF_ZB     = 69216018LL;   // 8*HW
constexpr long long OFF_P      = 71313170LL;   // 8*HW
constexpr long long OFF_D      = 73410322LL;   // 8*HW
constexpr long long OFF_BC     = 75507474LL;   // 8*HW*3
// total = 81798930

__device__ int g_face_flag[F_];

// ---------------------------------------------------------------------------
// Kernel 1: reset face flags + zero the vertex-visibility output region.
// Must run every launch (graph replays must be deterministic).
// ---------------------------------------------------------------------------
__global__ void init_k(float* __restrict__ out) {
    int i = blockIdx.x * blockDim.x + threadIdx.x;
    if (i < F_) g_face_flag[i] = 0;
    if (i < V_) out[OFF_VV + i] = 0.0f;
}

// ---------------------------------------------------------------------------
// Kernel 2: fused per-pixel pass. Each thread owns 4 consecutive w-pixels so
// out_map stores are float4 and fully coalesced across the warp.
// ---------------------------------------------------------------------------
__global__ __launch_bounds__(256) void pixel_k(
    const float* __restrict__ zbuf,
    const int*   __restrict__ ptf,
    const float* __restrict__ bary,
    const float* __restrict__ dists,
    const float* __restrict__ fm,
    float*       __restrict__ out)
{
    int g = blockIdx.x * blockDim.x + threadIdx.x;  // 0 .. HW/4-1
    int pix = g << 2;

    // ---- pass 1: coverage count + argmin over the 8 layers -----------------
    float z[8][4];
    float minv[4];
    int   mini[4];
    int   cnt[4];
#pragma unroll
    for (int j = 0; j < 4; j++) { minv[j] = 3.0e38f; mini[j] = 0; cnt[j] = 0; }

#pragma unroll
    for (int n = 0; n < 8; n++) {
        float4 zz = *(const float4*)(zbuf + n * HW + pix);
        z[n][0] = zz.x; z[n][1] = zz.y; z[n][2] = zz.z; z[n][3] = zz.w;
#pragma unroll
        for (int j = 0; j < 4; j++) {
            float v = z[n][j];
            cnt[j] += (v > -1.0f) ? 1 : 0;
            float tmp = (v < 0.0f) ? BIGZ : v;
            if (tmp < minv[j]) { minv[j] = tmp; mini[j] = n; }  // first-min (argmin)
        }
    }

    // ---- pass 2: per layer, emit masked outputs + colors -------------------
#pragma unroll
    for (int n = 0; n < 8; n++) {
        int4   pf4 = *(const int4*)(ptf + n * HW + pix);
        float4 d4  = *(const float4*)(dists + n * HW + pix);
        const float* bptr = bary + (long long)(n * HW + pix) * 3;
        float4 bA = *(const float4*)(bptr);
        float4 bB = *(const float4*)(bptr + 4);
        float4 bC = *(const float4*)(bptr + 8);
        float bin[12] = {bA.x, bA.y, bA.z, bA.w, bB.x, bB.y, bB.z, bB.w,
                         bC.x, bC.y, bC.z, bC.w};
        int   pf[4] = {pf4.x, pf4.y, pf4.z, pf4.w};
        float dd[4] = {d4.x, d4.y, d4.z, d4.w};

        float zbo[4], po[4], dto[4], mo[4], bco[12];
        float b0[4], b1[4], b2[4];
        int   pr[4];
        bool  valid[4];
#pragma unroll
        for (int j = 0; j < 4; j++) {
            bool dup = (cnt[j] > 1) && (mini[j] != n);
            int  p   = dup ? -1 : pf[j];
            valid[j] = (p >= 0);
            pr[j]    = valid[j] ? p : 0;
            zbo[j]   = dup ? -1.0f : z[n][j];
            po[j]    = (float)p;
            dto[j]   = dup ? -1.0f : dd[j];
            b0[j]    = dup ? -1.0f : bin[3 * j + 0];
            b1[j]    = dup ? -1.0f : bin[3 * j + 1];
            b2[j]    = dup ? -1.0f : bin[3 * j + 2];
            bco[3 * j + 0] = b0[j];
            bco[3 * j + 1] = b1[j];
            bco[3 * j + 2] = b2[j];
            mo[j] = (z[n][j] >= 0.0f) ? 1.0f : 0.0f;
            if (valid[j]) g_face_flag[pr[j]] = 1;  // idempotent flag store
        }

        // small outputs — regions are only 8B-aligned (offsets ≡ 2 mod 4),
        // so use float2 stores.
        long long base = (long long)n * HW + pix;
        float* zp = out + OFF_ZB + base;
        *(float2*)(zp)     = make_float2(zbo[0], zbo[1]);
        *(float2*)(zp + 2) = make_float2(zbo[2], zbo[3]);
        float* pp = out + OFF_P + base;
        *(float2*)(pp)     = make_float2(po[0], po[1]);
        *(float2*)(pp + 2) = make_float2(po[2], po[3]);
        float* dp = out + OFF_D + base;
        *(float2*)(dp)     = make_float2(dto[0], dto[1]);
        *(float2*)(dp + 2) = make_float2(dto[2], dto[3]);
        float* mp = out + OFF_MASK + base;
        *(float2*)(mp)     = make_float2(mo[0], mo[1]);
        *(float2*)(mp + 2) = make_float2(mo[2], mo[3]);
        float* bp = out + OFF_BC + base * 3;
#pragma unroll
        for (int k = 0; k < 6; k++)
            *(float2*)(bp + 2 * k) = make_float2(bco[2 * k], bco[2 * k + 1]);

        // colors: out_map[n][c][h][w]; float4 over w, transposed in regs
        float* om = out + OFF_OUTMAP + (long long)n * C_ * HW + pix;
#pragma unroll
        for (int cq = 0; cq < 8; cq++) {
            int c = cq * 4;
            float col[4][4];
#pragma unroll
            for (int j = 0; j < 4; j++) {
                float4 a = make_float4(0.f, 0.f, 0.f, 0.f);
                if (valid[j]) {
                    const float* fb = fm + pr[j] * 96 + c;  // face_memory[p][i][c]
                    float4 f0 = *(const float4*)(fb);
                    float4 f1 = *(const float4*)(fb + 32);
                    float4 f2 = *(const float4*)(fb + 64);
                    a.x = b0[j] * f0.x + b1[j] * f1.x + b2[j] * f2.x;
                    a.y = b0[j] * f0.y + b1[j] * f1.y + b2[j] * f2.y;
                    a.z = b0[j] * f0.z + b1[j] * f1.z + b2[j] * f2.z;
                    a.w = b0[j] * f0.w + b1[j] * f1.w + b2[j] * f2.w;
                }
                col[j][0] = a.x; col[j][1] = a.y; col[j][2] = a.z; col[j][3] = a.w;
            }
#pragma unroll
            for (int k = 0; k < 4; k++)
                *(float4*)(om + (long long)(c + k) * HW) =
                    make_float4(col[0][k], col[1][k], col[2][k], col[3][k]);
        }
    }
}

// ---------------------------------------------------------------------------
// Kernel 3: face visibility -> vertex visibility scatter (idempotent stores).
// ---------------------------------------------------------------------------
__global__ void vertex_k(const int* __restrict__ faces, float* __restrict__ out) {
    int f = blockIdx.x * blockDim.x + threadIdx.x;
    if (f < F_ && g_face_flag[f]) {
        out[OFF_VV + faces[3 * f + 0]] = 1.0f;
        out[OFF_VV + faces[3 * f + 1]] = 1.0f;
        out[OFF_VV + faces[3 * f + 2]] = 1.0f;
    }
}

extern "C" void kernel_launch(void* const* d_in, const int* in_sizes, int n_in,
                              void* d_out, int out_size) {
    const float* zbuf  = (const float*)d_in[0];
    const int*   ptf   = (const int*)d_in[1];
    const float* bary  = (const float*)d_in[2];
    const float* dists = (const float*)d_in[3];
    const float* fm    = (const float*)d_in[4];
    const int*   faces = (const int*)d_in[5];
    float* out = (float*)d_out;

    init_k<<<(F_ + 255) / 256, 256>>>(out);
    pixel_k<<<(HW / 4) / 256, 256>>>(zbuf, ptf, bary, dists, fm, out);
    vertex_k<<<(F_ + 255) / 256, 256>>>(faces, out);
}

// round 2
// speedup vs baseline: 1.0870x; 1.0870x over previous
#include <cuda_runtime.h>

#define BIGZ 1000000.0f
constexpr int N_ = 8, H_ = 512, W_ = 512, C_ = 32, F_ = 20000, V_ = 10002;
constexpr int HW = H_ * W_;  // 262144

// Output concatenation offsets (float32 elements)
constexpr long long OFF_OUTMAP = 0LL;
constexpr long long OFF_VV     = 67108864LL;
constexpr long long OFF_MASK   = 67118866LL;
constexpr long long OFF_ZB     = 69216018LL;
constexpr long long OFF_P      = 71313170LL;
constexpr long long OFF_D      = 73410322LL;
constexpr long long OFF_BC     = 75507474LL;

// zero-initialized at module load; vertex_k restores all-zero after each use,
// so every graph replay sees the same initial state.
__device__ int g_face_flag[F_];

__device__ __forceinline__ void stcs4(float* p, float a, float b, float c, float d) {
    float4 v = make_float4(a, b, c, d);
    __stcs((float4*)p, v);
}
__device__ __forceinline__ void stcs2(float* p, float a, float b) {
    float2 v = make_float2(a, b);
    __stcs((float2*)p, v);
}

// ---------------------------------------------------------------------------
// Fused per-pixel pass. 4 consecutive w-pixels per thread (float4 stores).
// Also zeroes the vertex-visibility output region (first V_ threads).
// ---------------------------------------------------------------------------
__global__ __launch_bounds__(128) void pixel_k(
    const float* __restrict__ zbuf,
    const int*   __restrict__ ptf,
    const float* __restrict__ bary,
    const float* __restrict__ dists,
    const float* __restrict__ fm,
    float*       __restrict__ out)
{
    int g = blockIdx.x * blockDim.x + threadIdx.x;  // 0 .. HW/4-1
    if (g < V_) out[OFF_VV + g] = 0.0f;
    int pix = g << 2;

    // ---- pass 1: coverage count + first-argmin over the 8 layers ----------
    float z[8][4];
    float minv[4];
    int   mini[4];
    int   cnt[4];
#pragma unroll
    for (int j = 0; j < 4; j++) { minv[j] = 3.0e38f; mini[j] = 0; cnt[j] = 0; }

#pragma unroll
    for (int n = 0; n < 8; n++) {
        float4 zz = __ldcs((const float4*)(zbuf + n * HW + pix));
        z[n][0] = zz.x; z[n][1] = zz.y; z[n][2] = zz.z; z[n][3] = zz.w;
#pragma unroll
        for (int j = 0; j < 4; j++) {
            float v = z[n][j];
            cnt[j] += (v > -1.0f) ? 1 : 0;
            float tmp = (v < 0.0f) ? BIGZ : v;
            if (tmp < minv[j]) { minv[j] = tmp; mini[j] = n; }
        }
    }

    // ---- pass 2: per layer, emit masked outputs + colors -------------------
#pragma unroll
    for (int n = 0; n < 8; n++) {
        int4   pf4 = __ldcs((const int4*)(ptf + n * HW + pix));
        float4 d4  = __ldcs((const float4*)(dists + n * HW + pix));
        const float* bptr = bary + (long long)(n * HW + pix) * 3;
        float4 bA = __ldcs((const float4*)(bptr));
        float4 bB = __ldcs((const float4*)(bptr + 4));
        float4 bC = __ldcs((const float4*)(bptr + 8));
        float bin[12] = {bA.x, bA.y, bA.z, bA.w, bB.x, bB.y, bB.z, bB.w,
                         bC.x, bC.y, bC.z, bC.w};
        int   pf[4] = {pf4.x, pf4.y, pf4.z, pf4.w};
        float dd[4] = {d4.x, d4.y, d4.z, d4.w};

        float zbo[4], po[4], dto[4], mo[4], bco[12];
        float b0[4], b1[4], b2[4];
        int   pr[4];
        bool  valid[4];
#pragma unroll
        for (int j = 0; j < 4; j++) {
            bool dup = (cnt[j] > 1) && (mini[j] != n);
            int  p   = dup ? -1 : pf[j];
            valid[j] = (p >= 0);
            pr[j]    = valid[j] ? p : 0;
            zbo[j]   = dup ? -1.0f : z[n][j];
            po[j]    = (float)p;
            dto[j]   = dup ? -1.0f : dd[j];
            b0[j]    = dup ? -1.0f : bin[3 * j + 0];
            b1[j]    = dup ? -1.0f : bin[3 * j + 1];
            b2[j]    = dup ? -1.0f : bin[3 * j + 2];
            bco[3 * j + 0] = b0[j];
            bco[3 * j + 1] = b1[j];
            bco[3 * j + 2] = b2[j];
            mo[j] = (z[n][j] >= 0.0f) ? 1.0f : 0.0f;
            if (valid[j]) g_face_flag[pr[j]] = 1;  // idempotent flag store
        }

        // small outputs: regions only 8B-aligned (offsets ≡ 2 mod 4) -> float2
        long long base = (long long)n * HW + pix;
        float* zp = out + OFF_ZB + base;
        stcs2(zp,     zbo[0], zbo[1]); stcs2(zp + 2, zbo[2], zbo[3]);
        float* pp = out + OFF_P + base;
        stcs2(pp,     po[0], po[1]);   stcs2(pp + 2, po[2], po[3]);
        float* dp = out + OFF_D + base;
        stcs2(dp,     dto[0], dto[1]); stcs2(dp + 2, dto[2], dto[3]);
        float* mp = out + OFF_MASK + base;
        stcs2(mp,     mo[0], mo[1]);   stcs2(mp + 2, mo[2], mo[3]);
        float* bp = out + OFF_BC + base * 3;
#pragma unroll
        for (int k = 0; k < 6; k++)
            stcs2(bp + 2 * k, bco[2 * k], bco[2 * k + 1]);

        // colors: out_map[n][c][h][w]; float4 over w, transposed in regs
        float* om = out + OFF_OUTMAP + (long long)n * C_ * HW + pix;
#pragma unroll
        for (int cq = 0; cq < 8; cq++) {
            int c = cq * 4;
            float col[4][4];
#pragma unroll
            for (int j = 0; j < 4; j++) {
                float4 a = make_float4(0.f, 0.f, 0.f, 0.f);
                if (valid[j]) {
                    const float* fb = fm + pr[j] * 96 + c;  // face_memory[p][i][c]
                    float4 f0 = *(const float4*)(fb);
                    float4 f1 = *(const float4*)(fb + 32);
                    float4 f2 = *(const float4*)(fb + 64);
                    a.x = b0[j] * f0.x + b1[j] * f1.x + b2[j] * f2.x;
                    a.y = b0[j] * f0.y + b1[j] * f1.y + b2[j] * f2.y;
                    a.z = b0[j] * f0.z + b1[j] * f1.z + b2[j] * f2.z;
                    a.w = b0[j] * f0.w + b1[j] * f1.w + b2[j] * f2.w;
                }
                col[j][0] = a.x; col[j][1] = a.y; col[j][2] = a.z; col[j][3] = a.w;
            }
#pragma unroll
            for (int k = 0; k < 4; k++)
                stcs4(om + (long long)(c + k) * HW,
                      col[0][k], col[1][k], col[2][k], col[3][k]);
        }
    }
}

// ---------------------------------------------------------------------------
// Face visibility -> vertex visibility scatter. Clears each flag after use so
// the next replay starts from the all-zero state (deterministic).
// ---------------------------------------------------------------------------
__global__ void vertex_k(const int* __restrict__ faces, float* __restrict__ out) {
    int f = blockIdx.x * blockDim.x + threadIdx.x;
    if (f < F_) {
        if (g_face_flag[f]) {
            out[OFF_VV + faces[3 * f + 0]] = 1.0f;
            out[OFF_VV + faces[3 * f + 1]] = 1.0f;
            out[OFF_VV + faces[3 * f + 2]] = 1.0f;
            g_face_flag[f] = 0;
        }
    }
}

extern "C" void kernel_launch(void* const* d_in, const int* in_sizes, int n_in,
                              void* d_out, int out_size) {
    const float* zbuf  = (const float*)d_in[0];
    const int*   ptf   = (const int*)d_in[1];
    const float* bary  = (const float*)d_in[2];
    const float* dists = (const float*)d_in[3];
    const float* fm    = (const float*)d_in[4];
    const int*   faces = (const int*)d_in[5];
    float* out = (float*)d_out;

    pixel_k<<<(HW / 4) / 128, 128>>>(zbuf, ptf, bary, dists, fm, out);
    vertex_k<<<(F_ + 255) / 256, 256>>>(faces, out);
}

// round 4
// speedup vs baseline: 1.0897x; 1.0025x over previous
#include <cuda_runtime.h>

#define BIGZ 1000000.0f
constexpr int N_ = 8, H_ = 512, W_ = 512, C_ = 32, F_ = 20000, V_ = 10002;
constexpr int HW = H_ * W_;  // 262144

// Output concatenation offsets (float32 elements)
constexpr long long OFF_OUTMAP = 0LL;
constexpr long long OFF_VV     = 67108864LL;
constexpr long long OFF_MASK   = 67118866LL;
constexpr long long OFF_ZB     = 69216018LL;
constexpr long long OFF_P      = 71313170LL;
constexpr long long OFF_D      = 73410322LL;
constexpr long long OFF_BC     = 75507474LL;

// zero-initialized at module load; vertex_k restores all-zero after each use,
// so every graph replay sees the same initial state.
__device__ int g_face_flag[F_];

__device__ __forceinline__ void stcs4(float* p, float a, float b, float c, float d) {
    float4 v = make_float4(a, b, c, d);
    __stcs((float4*)p, v);
}
__device__ __forceinline__ void stcs2(float* p, float a, float b) {
    float2 v = make_float2(a, b);
    __stcs((float2*)p, v);
}

// ---------------------------------------------------------------------------
// Fused per-pixel pass. 4 consecutive w-pixels per thread (float4 stores).
// Also zeroes the vertex-visibility output region (first V_ threads).
// block=64 / grid=1024: fine-grained CTAs so per-SM wave quantization ~1%.
// ---------------------------------------------------------------------------
__global__ __launch_bounds__(64) void pixel_k(
    const float* __restrict__ zbuf,
    const int*   __restrict__ ptf,
    const float* __restrict__ bary,
    const float* __restrict__ dists,
    const float* __restrict__ fm,
    float*       __restrict__ out)
{
    int g = blockIdx.x * blockDim.x + threadIdx.x;  // 0 .. HW/4-1
    if (g < V_) out[OFF_VV + g] = 0.0f;
    int pix = g << 2;

    // ---- pass 1: coverage count + first-argmin over the 8 layers ----------
    float z[8][4];
    float minv[4];
    int   mini[4];
    int   cnt[4];
#pragma unroll
    for (int j = 0; j < 4; j++) { minv[j] = 3.0e38f; mini[j] = 0; cnt[j] = 0; }

#pragma unroll
    for (int n = 0; n < 8; n++) {
        float4 zz = __ldcs((const float4*)(zbuf + n * HW + pix));
        z[n][0] = zz.x; z[n][1] = zz.y; z[n][2] = zz.z; z[n][3] = zz.w;
#pragma unroll
        for (int j = 0; j < 4; j++) {
            float v = z[n][j];
            cnt[j] += (v > -1.0f) ? 1 : 0;
            float tmp = (v < 0.0f) ? BIGZ : v;
            if (tmp < minv[j]) { minv[j] = tmp; mini[j] = n; }
        }
    }

    // ---- pass 2: per layer, emit masked outputs + colors -------------------
#pragma unroll
    for (int n = 0; n < 8; n++) {
        int4   pf4 = __ldcs((const int4*)(ptf + n * HW + pix));
        float4 d4  = __ldcs((const float4*)(dists + n * HW + pix));
        const float* bptr = bary + (long long)(n * HW + pix) * 3;
        float4 bA = __ldcs((const float4*)(bptr));
        float4 bB = __ldcs((const float4*)(bptr + 4));
        float4 bC = __ldcs((const float4*)(bptr + 8));
        float bin[12] = {bA.x, bA.y, bA.z, bA.w, bB.x, bB.y, bB.z, bB.w,
                         bC.x, bC.y, bC.z, bC.w};
        int   pf[4] = {pf4.x, pf4.y, pf4.z, pf4.w};
        float dd[4] = {d4.x, d4.y, d4.z, d4.w};

        float zbo[4], po[4], dto[4], mo[4], bco[12];
        float b0[4], b1[4], b2[4];
        int   pr[4];
        bool  valid[4];
#pragma unroll
        for (int j = 0; j < 4; j++) {
            bool dup = (cnt[j] > 1) && (mini[j] != n);
            int  p   = dup ? -1 : pf[j];
            valid[j] = (p >= 0);
            pr[j]    = valid[j] ? p : 0;
            zbo[j]   = dup ? -1.0f : z[n][j];
            po[j]    = (float)p;
            dto[j]   = dup ? -1.0f : dd[j];
            b0[j]    = dup ? -1.0f : bin[3 * j + 0];
            b1[j]    = dup ? -1.0f : bin[3 * j + 1];
            b2[j]    = dup ? -1.0f : bin[3 * j + 2];
            bco[3 * j + 0] = b0[j];
            bco[3 * j + 1] = b1[j];
            bco[3 * j + 2] = b2[j];
            mo[j] = (z[n][j] >= 0.0f) ? 1.0f : 0.0f;
            if (valid[j]) g_face_flag[pr[j]] = 1;  // idempotent flag store
        }

        // small outputs: regions only 8B-aligned (offsets ≡ 2 mod 4) -> float2
        long long base = (long long)n * HW + pix;
        float* zp = out + OFF_ZB + base;
        stcs2(zp,     zbo[0], zbo[1]); stcs2(zp + 2, zbo[2], zbo[3]);
        float* pp = out + OFF_P + base;
        stcs2(pp,     po[0], po[1]);   stcs2(pp + 2, po[2], po[3]);
        float* dp = out + OFF_D + base;
        stcs2(dp,     dto[0], dto[1]); stcs2(dp + 2, dto[2], dto[3]);
        float* mp = out + OFF_MASK + base;
        stcs2(mp,     mo[0], mo[1]);   stcs2(mp + 2, mo[2], mo[3]);
        float* bp = out + OFF_BC + base * 3;
#pragma unroll
        for (int k = 0; k < 6; k++)
            stcs2(bp + 2 * k, bco[2 * k], bco[2 * k + 1]);

        // colors: out_map[n][c][h][w]; float4 over w, transposed in regs
        float* om = out + OFF_OUTMAP + (long long)n * C_ * HW + pix;
#pragma unroll
        for (int cq = 0; cq < 8; cq++) {
            int c = cq * 4;
            float col[4][4];
#pragma unroll
            for (int j = 0; j < 4; j++) {
                float4 a = make_float4(0.f, 0.f, 0.f, 0.f);
                if (valid[j]) {
                    const float* fb = fm + pr[j] * 96 + c;  // face_memory[p][i][c]
                    float4 f0 = *(const float4*)(fb);
                    float4 f1 = *(const float4*)(fb + 32);
                    float4 f2 = *(const float4*)(fb + 64);
                    a.x = b0[j] * f0.x + b1[j] * f1.x + b2[j] * f2.x;
                    a.y = b0[j] * f0.y + b1[j] * f1.y + b2[j] * f2.y;
                    a.z = b0[j] * f0.z + b1[j] * f1.z + b2[j] * f2.z;
                    a.w = b0[j] * f0.w + b1[j] * f1.w + b2[j] * f2.w;
                }
                col[j][0] = a.x; col[j][1] = a.y; col[j][2] = a.z; col[j][3] = a.w;
            }
#pragma unroll
            for (int k = 0; k < 4; k++)
                stcs4(om + (long long)(c + k) * HW,
                      col[0][k], col[1][k], col[2][k], col[3][k]);
        }
    }
}

// ---------------------------------------------------------------------------
// Face visibility -> vertex visibility scatter. faces[] is loaded in PARALLEL
// with the flag (no dependent chain), stores are predicated on the flag.
// Clears each flag after use so the next replay starts from all-zero state.
// ---------------------------------------------------------------------------
__global__ __launch_bounds__(128) void vertex_k(const int* __restrict__ faces,
                                                float* __restrict__ out) {
    int f = blockIdx.x * blockDim.x + threadIdx.x;
    if (f < F_) {
        // issue both loads before consuming either (independent, overlap)
        int flag = g_face_flag[f];
        int v0 = __ldg(faces + 3 * f + 0);
        int v1 = __ldg(faces + 3 * f + 1);
        int v2 = __ldg(faces + 3 * f + 2);
        if (flag) {
            out[OFF_VV + v0] = 1.0f;
            out[OFF_VV + v1] = 1.0f;
            out[OFF_VV + v2] = 1.0f;
            g_face_flag[f] = 0;
        }
    }
}

extern "C" void kernel_launch(void* const* d_in, const int* in_sizes, int n_in,
                              void* d_out, int out_size) {
    const float* zbuf  = (const float*)d_in[0];
    const int*   ptf   = (const int*)d_in[1];
    const float* bary  = (const float*)d_in[2];
    const float* dists = (const float*)d_in[3];
    const float* fm    = (const float*)d_in[4];
    const int*   faces = (const int*)d_in[5];
    float* out = (float*)d_out;

    pixel_k<<<(HW / 4) / 64, 64>>>(zbuf, ptf, bary, dists, fm, out);
    vertex_k<<<(F_ + 127) / 128, 128>>>(faces, out);
}